// round 7
// baseline (speedup 1.0000x reference)
#include <cuda_runtime.h>
#include <cuda_bf16.h>
#include <cstdint>
#include <math.h>

// ---------------- problem constants ----------------
#define D_MODEL  2048
#define N_HEADS  16
#define HEAD_DIM 128
#define BATCH    2
#define SEQ      2048
#define M_TOT    (BATCH * SEQ)      // 4096 rows
#define N_QKV    (3 * D_MODEL)      // 6144 fused QKV width

// ---------------- scratch (alloc-free rule: __device__ globals) ----------------
__device__ float g_QKV[M_TOT * N_QKV];     // [token][Q(2048) | K(2048) | V(2048)]
__device__ float g_C[M_TOT * D_MODEL];     // attention context

__device__ __nv_bfloat16 g_xh[M_TOT * D_MODEL];
__device__ __nv_bfloat16 g_xl[M_TOT * D_MODEL];
__device__ __nv_bfloat16 g_ch[M_TOT * D_MODEL];
__device__ __nv_bfloat16 g_cl[M_TOT * D_MODEL];
__device__ __nv_bfloat16 g_Wh[4 * D_MODEL * D_MODEL];   // Wq,Wk,Wv,Wo packed
__device__ __nv_bfloat16 g_Wl[4 * D_MODEL * D_MODEL];

// ============================================================================
// PTX helpers (compute_103-safe: mma.sync / ldmatrix / cp.async only)
// ============================================================================
__device__ __forceinline__ uint32_t smem_u32(const void* p) {
    uint32_t a;
    asm("{ .reg .u64 t; cvta.to.shared.u64 t, %1; cvt.u32.u64 %0, t; }" : "=r"(a) : "l"(p));
    return a;
}
__device__ __forceinline__ void ldmatrix_x4(uint32_t* r, uint32_t addr) {
    asm volatile("ldmatrix.sync.aligned.m8n8.x4.shared.b16 {%0,%1,%2,%3}, [%4];"
                 : "=r"(r[0]), "=r"(r[1]), "=r"(r[2]), "=r"(r[3]) : "r"(addr));
}
__device__ __forceinline__ void mma_bf16(float* c, const uint32_t* a, const uint32_t* b) {
    asm volatile(
        "mma.sync.aligned.m16n8k16.row.col.f32.bf16.bf16.f32 "
        "{%0,%1,%2,%3}, {%4,%5,%6,%7}, {%8,%9}, {%0,%1,%2,%3};"
        : "+f"(c[0]), "+f"(c[1]), "+f"(c[2]), "+f"(c[3])
        : "r"(a[0]), "r"(a[1]), "r"(a[2]), "r"(a[3]), "r"(b[0]), "r"(b[1]));
}
__device__ __forceinline__ void cp16(uint32_t s, const void* g) {
    asm volatile("cp.async.cg.shared.global [%0], [%1], 16;" :: "r"(s), "l"(g));
}
__device__ __forceinline__ void cp_commit() {
    asm volatile("cp.async.commit_group;" ::: "memory");
}
__device__ __forceinline__ void cp_wait2() {
    asm volatile("cp.async.wait_group 2;" ::: "memory");
}

// ============================================================================
// fp32 -> bf16 hi/lo split conversion (vectorized)
// ============================================================================
__global__ void cvt_kernel(const float* __restrict__ in,
                           __nv_bfloat16* __restrict__ hi,
                           __nv_bfloat16* __restrict__ lo, int n4)
{
    int i = blockIdx.x * blockDim.x + threadIdx.x;
    if (i >= n4) return;
    float4 v = ((const float4*)in)[i];
    __nv_bfloat16 h0 = __float2bfloat16(v.x), h1 = __float2bfloat16(v.y);
    __nv_bfloat16 h2 = __float2bfloat16(v.z), h3 = __float2bfloat16(v.w);
    __nv_bfloat16 l0 = __float2bfloat16(v.x - __bfloat162float(h0));
    __nv_bfloat16 l1 = __float2bfloat16(v.y - __bfloat162float(h1));
    __nv_bfloat16 l2 = __float2bfloat16(v.z - __bfloat162float(h2));
    __nv_bfloat16 l3 = __float2bfloat16(v.w - __bfloat162float(h3));
    __nv_bfloat162* hp = (__nv_bfloat162*)hi;
    __nv_bfloat162* lp = (__nv_bfloat162*)lo;
    __nv_bfloat162 a; a.x = h0; a.y = h1; hp[2*i] = a;
    __nv_bfloat162 b; b.x = h2; b.y = h3; hp[2*i+1] = b;
    __nv_bfloat162 c; c.x = l0; c.y = l1; lp[2*i] = c;
    __nv_bfloat162 d; d.x = l2; d.y = l3; lp[2*i+1] = d;
}

// ============================================================================
// bf16x3 GEMM via mma.sync: C[m,n] = sum_k A[m,k]*B[n,k]
// CTA 128(M)x64(N), 128 threads (4 warps, warp tile 64x32).
// BK=32, 3-stage cp.async pipeline (24KB/stage), prefetch issued at loop top.
// 3 CTAs/SM (launch_bounds(128,3)): 12 warps/SM for latency hiding.
// ============================================================================
#define BK        32
#define NITER     (D_MODEL / BK)          // 64
#define OFF_AH    0
#define OFF_AL    8192
#define OFF_BH    16384
#define OFF_BL    20480
#define STAGE_B3  24576                   // 24 KB per stage
#define SMEM_GEMM (3 * STAGE_B3 + 128)    // 72 KB + align pad

__device__ __forceinline__ uint32_t sw_off(int row, int chunk) {
    return (uint32_t)(row * 64 + ((chunk ^ ((row >> 1) & 3)) << 4));
}

__device__ __forceinline__ void issue_stage(
    uint32_t stage,
    const __nv_bfloat16* __restrict__ Ah, const __nv_bfloat16* __restrict__ Al,
    const __nv_bfloat16* __restrict__ Bh, const __nv_bfloat16* __restrict__ Bl,
    int bm, int bn, int k0, int tid)
{
    // A tiles: 128 rows x 4 x 16B chunks (Ah + Al)
#pragma unroll
    for (int j = 0; j < 4; j++) {
        int idx = tid + 128 * j;            // 0..511
        int row = idx >> 2;
        int ch  = idx & 3;
        uint32_t so = sw_off(row, ch);
        size_t ga = (size_t)(bm + row) * D_MODEL + k0 + ch * 8;
        cp16(stage + OFF_AH + so, Ah + ga);
        cp16(stage + OFF_AL + so, Al + ga);
    }
    // B tiles: 64 rows x 4 chunks (Bh + Bl)
#pragma unroll
    for (int j = 0; j < 2; j++) {
        int idx = tid + 128 * j;            // 0..255
        int row = idx >> 2;
        int ch  = idx & 3;
        uint32_t so = sw_off(row, ch);
        size_t gb = (size_t)(bn + row) * D_MODEL + k0 + ch * 8;
        cp16(stage + OFF_BH + so, Bh + gb);
        cp16(stage + OFF_BL + so, Bl + gb);
    }
}

__global__ void __launch_bounds__(128, 3) mma_gemm_kernel(
    const __nv_bfloat16* __restrict__ Ah, const __nv_bfloat16* __restrict__ Al,
    const __nv_bfloat16* __restrict__ Bh, const __nv_bfloat16* __restrict__ Bl,
    float* __restrict__ C, int ldc)
{
    extern __shared__ char sm_raw[];
    const uint32_t sbase = (smem_u32(sm_raw) + 127u) & ~127u;

    const int tid  = threadIdx.x;
    const int lane = tid & 31;
    const int w    = tid >> 5;
    const int wm   = (w & 1) * 64;      // warp m offset (0/64)
    const int wn   = (w >> 1) * 32;     // warp n offset (0/32)
    const int bm   = blockIdx.y * 128;
    const int bn   = blockIdx.x * 64;

    // ldmatrix lane addressing (verified in R5)
    const int g  = lane >> 3;
    const int li = lane & 7;
    const int aRowL = li + ((g & 1) << 3);
    const int aChL  = g >> 1;
    const int bRowL = li + ((g >> 1) << 3);
    const int bChL  = g & 1;

    float acc[4][4][4];
#pragma unroll
    for (int mi = 0; mi < 4; mi++)
#pragma unroll
        for (int ni = 0; ni < 4; ni++)
#pragma unroll
            for (int r = 0; r < 4; r++) acc[mi][ni][r] = 0.f;

    // prologue: stages 0,1
    issue_stage(sbase + 0 * STAGE_B3, Ah, Al, Bh, Bl, bm, bn, 0, tid);
    cp_commit();
    issue_stage(sbase + 1 * STAGE_B3, Ah, Al, Bh, Bl, bm, bn, BK, tid);
    cp_commit();

    int buf = 0;                 // buffer index of iteration c (c % 3)
    int nbuf = 2;                // buffer index for c+2
    for (int c = 0; c < NITER; c++) {
        // prefetch stage c+2 at loop top (buffer was consumed in iter c-1)
        if (c + 2 < NITER)
            issue_stage(sbase + (uint32_t)nbuf * STAGE_B3, Ah, Al, Bh, Bl,
                        bm, bn, (c + 2) * BK, tid);
        cp_commit();
        cp_wait2();               // ensure stage c complete (<=2 groups pending)
        __syncthreads();

        const uint32_t st  = sbase + (uint32_t)buf * STAGE_B3;
        const uint32_t tAh = st + OFF_AH;
        const uint32_t tAl = st + OFF_AL;
        const uint32_t tBh = st + OFF_BH;
        const uint32_t tBl = st + OFF_BL;

#pragma unroll
        for (int ks = 0; ks < 2; ks++) {
            const int aCh = 2 * ks + aChL;
            const int bCh = 2 * ks + bChL;

            uint32_t ah[4][4], bh[4][2], bl[4][2];
#pragma unroll
            for (int mi = 0; mi < 4; mi++)
                ldmatrix_x4(ah[mi], tAh + sw_off(wm + mi * 16 + aRowL, aCh));
#pragma unroll
            for (int p = 0; p < 2; p++) {
                uint32_t t4[4];
                ldmatrix_x4(t4, tBh + sw_off(wn + p * 16 + bRowL, bCh));
                bh[2 * p][0] = t4[0]; bh[2 * p][1] = t4[1];
                bh[2 * p + 1][0] = t4[2]; bh[2 * p + 1][1] = t4[3];
                ldmatrix_x4(t4, tBl + sw_off(wn + p * 16 + bRowL, bCh));
                bl[2 * p][0] = t4[0]; bl[2 * p][1] = t4[1];
                bl[2 * p + 1][0] = t4[2]; bl[2 * p + 1][1] = t4[3];
            }

#pragma unroll
            for (int mi = 0; mi < 4; mi++)
#pragma unroll
                for (int ni = 0; ni < 4; ni++)
                    mma_bf16(acc[mi][ni], ah[mi], bh[ni]);
#pragma unroll
            for (int mi = 0; mi < 4; mi++)
#pragma unroll
                for (int ni = 0; ni < 4; ni++)
                    mma_bf16(acc[mi][ni], ah[mi], bl[ni]);

            uint32_t al[4][4];
#pragma unroll
            for (int mi = 0; mi < 4; mi++)
                ldmatrix_x4(al[mi], tAl + sw_off(wm + mi * 16 + aRowL, aCh));
#pragma unroll
            for (int mi = 0; mi < 4; mi++)
#pragma unroll
                for (int ni = 0; ni < 4; ni++)
                    mma_bf16(acc[mi][ni], al[mi], bh[ni]);
        }
        __syncthreads();          // all warps done with buf before it is refilled

        buf  = (buf == 2)  ? 0 : buf + 1;
        nbuf = (nbuf == 2) ? 0 : nbuf + 1;
    }

    // epilogue: direct float2 stores
    const int gid = lane >> 2;
    const int tig = lane & 3;
#pragma unroll
    for (int mi = 0; mi < 4; mi++) {
#pragma unroll
        for (int ni = 0; ni < 4; ni++) {
            int row = bm + wm + mi * 16 + gid;
            int col = bn + wn + ni * 8 + tig * 2;
            float2 v0 = make_float2(acc[mi][ni][0], acc[mi][ni][1]);
            float2 v1 = make_float2(acc[mi][ni][2], acc[mi][ni][3]);
            *(float2*)(C + (size_t)row * ldc + col) = v0;
            *(float2*)(C + (size_t)(row + 8) * ldc + col) = v1;
        }
    }
}

// ============================================================================
// RoPE in-place on the fused QKV buffer (Q at col 0, K at col 2048; stride 6144)
// ============================================================================
__global__ void rope_kernel(float* __restrict__ QKV, const int* __restrict__ pos)
{
    int idx = blockIdx.x * blockDim.x + threadIdx.x;
    const int total = BATCH * SEQ * N_HEADS * (HEAD_DIM / 2);
    if (idx >= total) return;

    int i  = idx & 63;
    int h  = (idx >> 6) & (N_HEADS - 1);
    int ss = (idx >> 10) & (SEQ - 1);
    int b  = idx >> 21;

    int p = pos[b * SEQ + ss];
    float inv_freq = powf(10000.0f, -(2.0f * (float)i) / 128.0f);
    float ang = (float)p * inv_freq;
    float s, c;
    sincosf(ang, &s, &c);

    size_t base = ((size_t)(b * SEQ + ss)) * N_QKV + h * HEAD_DIM + 2 * i;
    float qe = QKV[base], qo = QKV[base + 1];
    QKV[base]     = qe * c - qo * s;
    QKV[base + 1] = qe * s + qo * c;
    size_t kb = base + D_MODEL;
    float ke = QKV[kb], ko = QKV[kb + 1];
    QKV[kb]     = ke * c - ko * s;
    QKV[kb + 1] = ke * s + ko * c;
}

// ============================================================================
// Causal flash attention, fp32. Q/K/V read from fused buffer (stride 6144),
// O written to g_C (stride 2048).
// ============================================================================
#define BQ 64
#define BKF 32

__global__ __launch_bounds__(256) void flash_kernel(const float* __restrict__ Q,
                                                    const float* __restrict__ K,
                                                    const float* __restrict__ V,
                                                    float* __restrict__ O)
{
    __shared__ float Ks[BKF][HEAD_DIM];
    __shared__ float Vs[BKF][HEAD_DIM];
    __shared__ float Ps[BQ][BKF];

    const int bh = blockIdx.y;
    const int b  = bh / N_HEADS;
    const int h  = bh % N_HEADS;
    const int q0 = blockIdx.x * BQ;

    const int tid  = threadIdx.x;
    const int row  = tid >> 2;
    const int part = tid & 3;
    const int qg   = q0 + row;

    const float scale = 0.08838834764831845f;

    float qf[32];
    const float* qp = Q + ((size_t)(b * SEQ + qg)) * N_QKV + h * HEAD_DIM + part * 32;
#pragma unroll
    for (int i = 0; i < 32; i += 4)
        *(float4*)(qf + i) = *(const float4*)(qp + i);

    float acc[32];
#pragma unroll
    for (int i = 0; i < 32; i++) acc[i] = 0.f;
    float m = -1e30f, l = 0.f;

    const int kend = q0 + BQ;
    for (int k0 = 0; k0 < kend; k0 += BKF) {
        __syncthreads();
        {
            const size_t rbase = (size_t)(b * SEQ + k0) * N_QKV + h * HEAD_DIM;
            for (int idx = tid; idx < BKF * (HEAD_DIM / 4); idx += 256) {
                int r = idx >> 5;
                int c = (idx & 31) * 4;
                ((float4*)Ks)[idx] = *(const float4*)(K + rbase + (size_t)r * N_QKV + c);
                ((float4*)Vs)[idx] = *(const float4*)(V + rbase + (size_t)r * N_QKV + c);
            }
        }
        __syncthreads();

        float sv[BKF / 4];
        float mblk = -1e30f;
#pragma unroll
        for (int j = 0; j < BKF; j++) {
            const float* kr = &Ks[j][part * 32];
            float d = 0.f;
#pragma unroll
            for (int i = 0; i < 32; i++) d = fmaf(qf[i], kr[i], d);
            d += __shfl_xor_sync(0xffffffffu, d, 1);
            d += __shfl_xor_sync(0xffffffffu, d, 2);
            d *= scale;
            int kg = k0 + j;
            d = (kg <= qg) ? d : -1e30f;
            if ((j & 3) == part) sv[j >> 2] = d;
            mblk = fmaxf(mblk, d);
        }

        float mnew  = fmaxf(m, mblk);
        float alpha = __expf(m - mnew);
        float ladd  = 0.f;
#pragma unroll
        for (int jj = 0; jj < BKF / 4; jj++) {
            float p = __expf(sv[jj] - mnew);
            ladd += p;
            Ps[row][jj * 4 + part] = p;
        }
        ladd += __shfl_xor_sync(0xffffffffu, ladd, 1);
        ladd += __shfl_xor_sync(0xffffffffu, ladd, 2);
        l = l * alpha + ladd;
        m = mnew;
#pragma unroll
        for (int i = 0; i < 32; i++) acc[i] *= alpha;
        __syncwarp();

#pragma unroll 4
        for (int j = 0; j < BKF; j++) {
            float p = Ps[row][j];
            const float* vr = &Vs[j][part * 32];
#pragma unroll
            for (int i = 0; i < 32; i++) acc[i] = fmaf(p, vr[i], acc[i]);
        }
    }

    float inv_l = 1.0f / l;
    float* op = O + ((size_t)(b * SEQ + qg)) * D_MODEL + h * HEAD_DIM + part * 32;
#pragma unroll
    for (int i = 0; i < 32; i++) op[i] = acc[i] * inv_l;
}

// ============================================================================
// launch
// ============================================================================
extern "C" void kernel_launch(void* const* d_in, const int* in_sizes, int n_in,
                              void* d_out, int out_size)
{
    const float* x   = (const float*)d_in[0];
    const int*   pos = (const int*)  d_in[1];
    const float* Wq  = (const float*)d_in[2];
    const float* Wk  = (const float*)d_in[3];
    const float* Wv  = (const float*)d_in[4];
    const float* Wo  = (const float*)d_in[5];
    float* out = (float*)d_out;

    float *QKVb, *Cb;
    __nv_bfloat16 *xh, *xl, *ch, *cl, *Wh, *Wl;
    cudaGetSymbolAddress((void**)&QKVb, g_QKV);
    cudaGetSymbolAddress((void**)&Cb, g_C);
    cudaGetSymbolAddress((void**)&xh, g_xh);
    cudaGetSymbolAddress((void**)&xl, g_xl);
    cudaGetSymbolAddress((void**)&ch, g_ch);
    cudaGetSymbolAddress((void**)&cl, g_cl);
    cudaGetSymbolAddress((void**)&Wh, g_Wh);
    cudaGetSymbolAddress((void**)&Wl, g_Wl);

    cudaFuncSetAttribute(mma_gemm_kernel,
                         cudaFuncAttributeMaxDynamicSharedMemorySize, SMEM_GEMM);

    const size_t WSZ = (size_t)D_MODEL * D_MODEL;
    const int x_n4 = (M_TOT * D_MODEL) / 4;
    const int w_n4 = (int)(WSZ / 4);

    // split conversions
    cvt_kernel<<<(x_n4 + 255) / 256, 256>>>(x, xh, xl, x_n4);
    cvt_kernel<<<(w_n4 + 255) / 256, 256>>>(Wq, Wh + 0 * WSZ, Wl + 0 * WSZ, w_n4);
    cvt_kernel<<<(w_n4 + 255) / 256, 256>>>(Wk, Wh + 1 * WSZ, Wl + 1 * WSZ, w_n4);
    cvt_kernel<<<(w_n4 + 255) / 256, 256>>>(Wv, Wh + 2 * WSZ, Wl + 2 * WSZ, w_n4);
    cvt_kernel<<<(w_n4 + 255) / 256, 256>>>(Wo, Wh + 3 * WSZ, Wl + 3 * WSZ, w_n4);

    // fused QKV projection: B rows 0..6143 = [Wq;Wk;Wv]
    dim3 qkvGrid(N_QKV / 64, M_TOT / 128);     // (96, 32)
    mma_gemm_kernel<<<qkvGrid, 128, SMEM_GEMM>>>(xh, xl, Wh, Wl, QKVb, N_QKV);

    int ropeTotal = BATCH * SEQ * N_HEADS * (HEAD_DIM / 2);
    rope_kernel<<<(ropeTotal + 255) / 256, 256>>>(QKVb, pos);

    dim3 flashGrid(SEQ / BQ, BATCH * N_HEADS);   // (32, 32)
    flash_kernel<<<flashGrid, 256>>>(QKVb, QKVb + D_MODEL, QKVb + 2 * D_MODEL, Cb);

    // output projection
    cvt_kernel<<<(x_n4 + 255) / 256, 256>>>(Cb, ch, cl, x_n4);
    dim3 oGrid(D_MODEL / 64, M_TOT / 128);       // (32, 32)
    mma_gemm_kernel<<<oGrid, 128, SMEM_GEMM>>>(ch, cl, Wh + 3 * WSZ, Wl + 3 * WSZ, out, D_MODEL);
}